// round 6
// baseline (speedup 1.0000x reference)
#include <cuda_runtime.h>

#define N_DOF 16
#define BATCH 64
#define SEQ 8192
#define CHUNK 64
#define NCHUNK (SEQ/CHUNK)          // 128
#define NSTATE 48
#define BSD ((size_t)BATCH*(size_t)SEQ*(size_t)N_DOF)

#define DTc 0.01f
#define CU_ 2.5e-5f   // (0.5-beta)*dt*dt
#define CV_ 0.005f    // (1-gamma)*dt
#define BU_ 2.5e-5f   // beta*dt*dt
#define BV_ 0.005f    // gamma*dt

// ---------------- packed f32x2 helpers (Blackwell FFMA2) ----------------
typedef unsigned long long u64;

__device__ __forceinline__ u64 ffma2(u64 a, u64 b, u64 c) {
    u64 d;
    asm("fma.rn.f32x2 %0, %1, %2, %3;" : "=l"(d) : "l"(a), "l"(b), "l"(c));
    return d;
}
__device__ __forceinline__ u64 fadd2(u64 a, u64 b) {
    u64 d;
    asm("add.rn.f32x2 %0, %1, %2;" : "=l"(d) : "l"(a), "l"(b));
    return d;
}
__device__ __forceinline__ float2 unpack2(u64 d) {
    float2 f;
    asm("mov.b64 {%0, %1}, %2;" : "=f"(f.x), "=f"(f.y) : "l"(d));
    return f;
}

// ---------------- scratch (device globals; no runtime allocation) ----------------
__device__ __align__(16) float g_Af[256];      // Af rows; read as packed pairs
__device__ __align__(16) float g_Wuv[16*32];   // interleaved pairs: (Au[i][j], Av[i][j])
__device__ __align__(16) float g_TL[NSTATE*NSTATE];
__device__ __align__(16) float g_e[(NCHUNK-1)*BATCH*NSTATE];
__device__ __align__(16) float g_init[NCHUNK*BATCH*NSTATE];

// ---------------- K0: setup ----------------
__device__ void invert16(const float* A, float* Ainv, double (*aug)[34], int tid)
{
    if (tid < 16) {
        #pragma unroll
        for (int j = 0; j < 16; j++) {
            aug[tid][j]      = (double)A[tid*16 + j];
            aug[tid][16 + j] = (tid == j) ? 1.0 : 0.0;
        }
    }
    __syncthreads();
    for (int k = 0; k < 16; k++) {
        if (tid == k) {
            double p = 1.0 / aug[k][k];
            #pragma unroll
            for (int j = 0; j < 32; j++) aug[k][j] *= p;
        }
        __syncthreads();
        if (tid < 16 && tid != k) {
            double f = aug[tid][k];
            #pragma unroll
            for (int j = 0; j < 32; j++) aug[tid][j] -= f * aug[k][j];
        }
        __syncthreads();
    }
    if (tid < 16) {
        #pragma unroll
        for (int j = 0; j < 16; j++) Ainv[tid*16 + j] = (float)aug[tid][16 + j];
    }
    __syncthreads();
}

__global__ void setup_kernel(const float* __restrict__ F,
                             const float* __restrict__ M,
                             const float* __restrict__ C,
                             const float* __restrict__ K,
                             float* __restrict__ out)
{
    __shared__ double aug[16][34];
    __shared__ float sM[256], sC[256], sK[256], sKe[256];
    __shared__ float sMinv[256], sAf[256], sAv[256], sAu[256];
    __shared__ __align__(16) float sT[NSTATE*NSTATE];
    __shared__ __align__(16) float sT2[NSTATE*NSTATE];

    const int tid = threadIdx.x;

    sM[tid] = M[tid]; sC[tid] = C[tid]; sK[tid] = K[tid];
    __syncthreads();

    invert16(sM, sMinv, aug, tid);

    sKe[tid] = sM[tid] + 0.5f*DTc*sC[tid] + 0.25f*DTc*DTc*sK[tid];
    __syncthreads();
    invert16(sKe, sAf, aug, tid);

    // A_v = A_f @ C, A_u = A_f @ K
    {
        int i = tid >> 4, j = tid & 15;
        float sv = 0.f, su = 0.f;
        #pragma unroll
        for (int k = 0; k < 16; k++) {
            sv = fmaf(sAf[i*16 + k], sC[k*16 + j], sv);
            su = fmaf(sAf[i*16 + k], sK[k*16 + j], su);
        }
        sAv[tid] = sv; sAu[tid] = su;
    }
    __syncthreads();

    g_Af[tid] = sAf[tid];
    {
        int i = tid >> 4, j = tid & 15;
        g_Wuv[i*32 + 2*j]     = sAu[tid];
        g_Wuv[i*32 + 2*j + 1] = sAv[tid];
    }

    // Build T (48x48) by pushing state basis vectors through one step (f = 0)
    if (tid < NSTATE) {
        float u[16], v[16], a[16];
        #pragma unroll
        for (int j = 0; j < 16; j++) {
            u[j] = (tid == j)      ? 1.f : 0.f;
            v[j] = (tid == j + 16) ? 1.f : 0.f;
            a[j] = (tid == j + 32) ? 1.f : 0.f;
        }
        float up[16], vp[16], an[16];
        #pragma unroll
        for (int i = 0; i < 16; i++) {
            up[i] = fmaf(CU_, a[i], fmaf(DTc, v[i], u[i]));
            vp[i] = fmaf(CV_, a[i], v[i]);
        }
        #pragma unroll
        for (int i = 0; i < 16; i++) {
            float s = 0.f;
            #pragma unroll
            for (int j = 0; j < 16; j++)
                s = fmaf(sAv[i*16 + j], vp[j], fmaf(sAu[i*16 + j], up[j], s));
            an[i] = -s;
        }
        #pragma unroll
        for (int i = 0; i < 16; i++) {
            sT[(i)     *NSTATE + tid] = fmaf(BU_, an[i], up[i]);
            sT[(16 + i)*NSTATE + tid] = fmaf(BV_, an[i], vp[i]);
            sT[(32 + i)*NSTATE + tid] = an[i];
        }
    }
    __syncthreads();

    // TL = T^64 via 6 squarings (ping-pong)
    float* Asq = sT;
    float* Bsq = sT2;
    for (int it = 0; it < 6; it++) {
        for (int e = tid; e < NSTATE*NSTATE; e += 256) {
            int r = e / NSTATE, cc = e % NSTATE;
            const float4* rowp = reinterpret_cast<const float4*>(Asq + r*NSTATE);
            float s0 = 0.f, s1 = 0.f, s2 = 0.f, s3 = 0.f;
            #pragma unroll
            for (int q = 0; q < 12; q++) {
                float4 m = rowp[q];
                s0 = fmaf(m.x, Asq[(4*q    )*NSTATE + cc], s0);
                s1 = fmaf(m.y, Asq[(4*q + 1)*NSTATE + cc], s1);
                s2 = fmaf(m.z, Asq[(4*q + 2)*NSTATE + cc], s2);
                s3 = fmaf(m.w, Asq[(4*q + 3)*NSTATE + cc], s3);
            }
            Bsq[e] = (s0 + s1) + (s2 + s3);
        }
        __syncthreads();
        float* t = Asq; Asq = Bsq; Bsq = t;
    }
    for (int e = tid; e < NSTATE*NSTATE; e += 256) g_TL[e] = Asq[e];

    // a0 = Minv @ F[b,0,:], write init_0 and t=0 output row
    for (int idx = tid; idx < BATCH*16; idx += 256) {
        int b = idx >> 4, i = idx & 15;
        const float* f0p = F + (size_t)b * SEQ * N_DOF;
        float s = 0.f;
        #pragma unroll
        for (int j = 0; j < 16; j++) s = fmaf(sMinv[i*16 + j], f0p[j], s);
        float* ip = g_init + (size_t)b * NSTATE;
        ip[i] = 0.f; ip[16 + i] = 0.f; ip[32 + i] = s;
        size_t o = ((size_t)b * SEQ) * N_DOF + i;
        out[o] = 0.f; out[BSD + o] = 0.f; out[2*BSD + o] = s;
    }
}

// ---------------- K1 / K3: chunked scans (packed f32x2 math) ----------------
template<bool FINAL>
__global__ void __launch_bounds__(256, 2) scan_kernel(const float* __restrict__ F,
                                                      float* __restrict__ out)
{
    const int tid  = threadIdx.x;
    const int lane = tid & 15;
    const int su   = tid >> 4;                 // 0..15
    const int unit = blockIdx.x * 16 + su;
    const int b    = unit & (BATCH - 1);
    const int c    = unit >> 6;

    // weights in registers, packed as f32x2 carriers (u64)
    const ulonglong2* Afp = reinterpret_cast<const ulonglong2*>(g_Af + lane*16);   // pairs (Af[2q],Af[2q+1])
    const ulonglong2 af01 = Afp[0], af23 = Afp[1], af45 = Afp[2], af67 = Afp[3];
    const ulonglong2* Wp = reinterpret_cast<const ulonglong2*>(g_Wuv + lane*32);   // pairs (Au[j],Av[j])
    ulonglong2 w0 = Wp[0], w1 = Wp[1], w2 = Wp[2], w3 = Wp[3];
    ulonglong2 w4 = Wp[4], w5 = Wp[5], w6 = Wp[6], w7 = Wp[7];

    float u, v, a;
    if (FINAL) {
        const float* ip = g_init + ((size_t)c * BATCH + b) * NSTATE;
        u = ip[lane]; v = ip[lane + 16]; a = ip[lane + 32];
    } else {
        u = 0.f; v = 0.f; a = 0.f;
    }

    __shared__ __align__(16) float2 sh[16][16];   // [unit][j] = (up_j, vp_j)
    float2* shp = sh[su];
    const ulonglong2* X2 = reinterpret_cast<const ulonglong2*>(shp);

    const float* Fb = F + (size_t)b * SEQ * N_DOF;
    const int t0 = c * CHUNK;

    // prefetch f for k=0 (time t0+1), as packed pairs
    ulonglong2 fA, fB, fC, fD;
    {
        int t = t0 + 1; if (t > SEQ - 1) t = SEQ - 1;
        const ulonglong2* fp = reinterpret_cast<const ulonglong2*>(Fb + (size_t)t * N_DOF);
        fA = fp[0]; fB = fp[1]; fC = fp[2]; fD = fp[3];
    }

    #pragma unroll 1
    for (int k = 0; k < CHUNK; k++) {
        // forcing dot (state-independent): 8 packed FMAs -> (sum_even, sum_odd)
        u64 accF0 = 0, accF1 = 0;
        accF0 = ffma2(af01.x, fA.x, accF0); accF1 = ffma2(af01.y, fA.y, accF1);
        accF0 = ffma2(af23.x, fB.x, accF0); accF1 = ffma2(af23.y, fB.y, accF1);
        accF0 = ffma2(af45.x, fC.x, accF0); accF1 = ffma2(af45.y, fC.y, accF1);
        accF0 = ffma2(af67.x, fD.x, accF0); accF1 = ffma2(af67.y, fD.y, accF1);

        const float up = fmaf(CU_, a, fmaf(DTc, v, u));
        const float vp = fmaf(CV_, a, v);
        shp[lane] = make_float2(up, vp);
        __syncwarp();

        // prefetch next step's f during the exchange shadow
        if (k + 1 < CHUNK) {
            int t = t0 + k + 2; if (t > SEQ - 1) t = SEQ - 1;
            const ulonglong2* fp = reinterpret_cast<const ulonglong2*>(Fb + (size_t)t * N_DOF);
            fA = fp[0]; fB = fp[1]; fC = fp[2]; fD = fp[3];
        }

        // exchange dot: 16 packed FMAs -> (sum Au*up, sum Av*vp)
        u64 accW0 = 0, accW1 = 0;
        {
            ulonglong2 x;
            x = X2[0]; accW0 = ffma2(w0.x, x.x, accW0); accW1 = ffma2(w0.y, x.y, accW1);
            x = X2[1]; accW0 = ffma2(w1.x, x.x, accW0); accW1 = ffma2(w1.y, x.y, accW1);
            x = X2[2]; accW0 = ffma2(w2.x, x.x, accW0); accW1 = ffma2(w2.y, x.y, accW1);
            x = X2[3]; accW0 = ffma2(w3.x, x.x, accW0); accW1 = ffma2(w3.y, x.y, accW1);
            x = X2[4]; accW0 = ffma2(w4.x, x.x, accW0); accW1 = ffma2(w4.y, x.y, accW1);
            x = X2[5]; accW0 = ffma2(w5.x, x.x, accW0); accW1 = ffma2(w5.y, x.y, accW1);
            x = X2[6]; accW0 = ffma2(w6.x, x.x, accW0); accW1 = ffma2(w6.y, x.y, accW1);
            x = X2[7]; accW0 = ffma2(w7.x, x.x, accW0); accW1 = ffma2(w7.y, x.y, accW1);
        }

        const float2 fS = unpack2(fadd2(accF0, accF1));
        const float2 wS = unpack2(fadd2(accW0, accW1));
        const float an = (fS.x + fS.y) - (wS.x + wS.y);
        const float un = fmaf(BU_, an, up);
        const float vn = fmaf(BV_, an, vp);

        if (FINAL) {
            const int t = t0 + k + 1;
            if (t < SEQ) {
                size_t o = ((size_t)b * SEQ + t) * N_DOF + lane;
                out[o]         = un;
                out[BSD + o]   = vn;
                out[2*BSD + o] = an;
            }
        }
        u = un; v = vn; a = an;
        __syncwarp();
    }

    if (!FINAL) {
        float* ep = g_e + ((size_t)c * BATCH + b) * NSTATE;
        ep[lane] = u; ep[lane + 16] = v; ep[lane + 32] = a;
    }
}

// ---------------- K2: sequential chunk chain (per batch, packed) ----------------
__global__ void chain_kernel()
{
    const int b = blockIdx.x;
    const int i = threadIdx.x;        // 0..47
    __shared__ __align__(16) float cur[2][NSTATE];

    // T row as 24 packed pairs
    ulonglong2 tl[12];
    {
        const ulonglong2* tp = reinterpret_cast<const ulonglong2*>(g_TL + i*NSTATE);
        #pragma unroll
        for (int q = 0; q < 12; q++) tl[q] = tp[q];
    }

    cur[0][i] = g_init[(size_t)b * NSTATE + i];
    __syncthreads();

    const float* ep = g_e + (size_t)b * NSTATE + i;
    const size_t estride = (size_t)BATCH * NSTATE;

    // prefetch ring (distance 2)
    float ev0 = ep[0];
    float ev1 = (NCHUNK > 2) ? ep[estride] : 0.f;

    int p = 0;
    for (int c = 1; c < NCHUNK; c++) {
        const float ev = ev0;
        ev0 = ev1;
        if (c + 2 < NCHUNK) ev1 = ep[(size_t)(c + 1) * estride];

        const ulonglong2* c2 = reinterpret_cast<const ulonglong2*>(cur[p]);
        u64 a0 = 0, a1 = 0, a2 = 0, a3 = 0;
        #pragma unroll
        for (int q = 0; q < 12; q += 4) {
            ulonglong2 x;
            x = c2[q];     a0 = ffma2(tl[q].x,     x.x, a0); a1 = ffma2(tl[q].y,     x.y, a1);
            x = c2[q + 1]; a2 = ffma2(tl[q + 1].x, x.x, a2); a3 = ffma2(tl[q + 1].y, x.y, a3);
            x = c2[q + 2]; a0 = ffma2(tl[q + 2].x, x.x, a0); a1 = ffma2(tl[q + 2].y, x.y, a1);
            x = c2[q + 3]; a2 = ffma2(tl[q + 3].x, x.x, a2); a3 = ffma2(tl[q + 3].y, x.y, a3);
        }
        const float2 s01 = unpack2(fadd2(a0, a1));
        const float2 s23 = unpack2(fadd2(a2, a3));
        const float r = ((s01.x + s01.y) + (s23.x + s23.y)) + ev;
        g_init[((size_t)c * BATCH + b) * NSTATE + i] = r;
        cur[1 - p][i] = r;
        __syncthreads();
        p ^= 1;
    }
}

// ---------------- launch ----------------
extern "C" void kernel_launch(void* const* d_in, const int* in_sizes, int n_in,
                              void* d_out, int out_size)
{
    const float* F = (const float*)d_in[0];
    const float* M = (const float*)d_in[1];
    const float* C = (const float*)d_in[2];
    const float* K = (const float*)d_in[3];
    float* out = (float*)d_out;

    setup_kernel<<<1, 256>>>(F, M, C, K, out);

    // K1: zero-init local scans for chunks 0..NCHUNK-2
    scan_kernel<false><<<(NCHUNK - 1) * BATCH / 16, 256>>>(F, nullptr);

    // K2: sequential combine across chunks, independent per batch
    chain_kernel<<<BATCH, NSTATE>>>();

    // K3: final scans from correct initial states, all chunks
    scan_kernel<true><<<NCHUNK * BATCH / 16, 256>>>(F, out);
}

// round 7
// speedup vs baseline: 1.0755x; 1.0755x over previous
#include <cuda_runtime.h>

#define N_DOF 16
#define BATCH 64
#define SEQ 8192
#define CHUNK 64
#define NCHUNK (SEQ/CHUNK)          // 128
#define NSTATE 48
#define BSD ((size_t)BATCH*(size_t)SEQ*(size_t)N_DOF)

#define DTc 0.01f
#define CU_ 2.5e-5f   // (0.5-beta)*dt*dt
#define CV_ 0.005f    // (1-gamma)*dt
#define BU_ 2.5e-5f   // beta*dt*dt
#define BV_ 0.005f    // gamma*dt

// ---------------- packed f32x2 helpers (Blackwell FFMA2) ----------------
typedef unsigned long long u64;

__device__ __forceinline__ u64 ffma2(u64 a, u64 b, u64 c) {
    u64 d;
    asm("fma.rn.f32x2 %0, %1, %2, %3;" : "=l"(d) : "l"(a), "l"(b), "l"(c));
    return d;
}
__device__ __forceinline__ u64 fadd2(u64 a, u64 b) {
    u64 d;
    asm("add.rn.f32x2 %0, %1, %2;" : "=l"(d) : "l"(a), "l"(b));
    return d;
}
__device__ __forceinline__ float2 unpack2(u64 d) {
    float2 f;
    asm("mov.b64 {%0, %1}, %2;" : "=f"(f.x), "=f"(f.y) : "l"(d));
    return f;
}

// ---------------- scratch (device globals; no runtime allocation) ----------------
__device__ __align__(16) float g_Af[256];      // K_eff^{-1}
__device__ __align__(16) float g_Wuv[16*32];   // interleaved pairs: (Au[i][j], Av[i][j])
__device__ __align__(16) float g_TL[NSTATE*NSTATE];
__device__ __align__(16) float g_e[(NCHUNK-1)*BATCH*NSTATE];
__device__ __align__(16) float g_init[NCHUNK*BATCH*NSTATE];
// PhiS[b][i][t'] = (A_f @ F[b, t'+1, :])[i]  for t' in [0, SEQ-1); PhiS[..][SEQ-1] = 0
__device__ __align__(16) float g_PhiS[(size_t)BATCH*N_DOF*SEQ];

// ---------------- K0: setup ----------------
__device__ void invert16(const float* A, float* Ainv, double (*aug)[34], int tid)
{
    if (tid < 16) {
        #pragma unroll
        for (int j = 0; j < 16; j++) {
            aug[tid][j]      = (double)A[tid*16 + j];
            aug[tid][16 + j] = (tid == j) ? 1.0 : 0.0;
        }
    }
    __syncthreads();
    for (int k = 0; k < 16; k++) {
        if (tid == k) {
            double p = 1.0 / aug[k][k];
            #pragma unroll
            for (int j = 0; j < 32; j++) aug[k][j] *= p;
        }
        __syncthreads();
        if (tid < 16 && tid != k) {
            double f = aug[tid][k];
            #pragma unroll
            for (int j = 0; j < 32; j++) aug[tid][j] -= f * aug[k][j];
        }
        __syncthreads();
    }
    if (tid < 16) {
        #pragma unroll
        for (int j = 0; j < 16; j++) Ainv[tid*16 + j] = (float)aug[tid][16 + j];
    }
    __syncthreads();
}

__global__ void setup_kernel(const float* __restrict__ F,
                             const float* __restrict__ M,
                             const float* __restrict__ C,
                             const float* __restrict__ K,
                             float* __restrict__ out)
{
    __shared__ double aug[16][34];
    __shared__ float sM[256], sC[256], sK[256], sKe[256];
    __shared__ float sMinv[256], sAf[256], sAv[256], sAu[256];
    __shared__ __align__(16) float sT[NSTATE*NSTATE];
    __shared__ __align__(16) float sT2[NSTATE*NSTATE];

    const int tid = threadIdx.x;

    sM[tid] = M[tid]; sC[tid] = C[tid]; sK[tid] = K[tid];
    __syncthreads();

    invert16(sM, sMinv, aug, tid);

    sKe[tid] = sM[tid] + 0.5f*DTc*sC[tid] + 0.25f*DTc*DTc*sK[tid];
    __syncthreads();
    invert16(sKe, sAf, aug, tid);

    // A_v = A_f @ C, A_u = A_f @ K
    {
        int i = tid >> 4, j = tid & 15;
        float sv = 0.f, su = 0.f;
        #pragma unroll
        for (int k = 0; k < 16; k++) {
            sv = fmaf(sAf[i*16 + k], sC[k*16 + j], sv);
            su = fmaf(sAf[i*16 + k], sK[k*16 + j], su);
        }
        sAv[tid] = sv; sAu[tid] = su;
    }
    __syncthreads();

    g_Af[tid] = sAf[tid];
    {
        int i = tid >> 4, j = tid & 15;
        g_Wuv[i*32 + 2*j]     = sAu[tid];
        g_Wuv[i*32 + 2*j + 1] = sAv[tid];
    }

    // Build T (48x48) by pushing state basis vectors through one step (f = 0)
    if (tid < NSTATE) {
        float u[16], v[16], a[16];
        #pragma unroll
        for (int j = 0; j < 16; j++) {
            u[j] = (tid == j)      ? 1.f : 0.f;
            v[j] = (tid == j + 16) ? 1.f : 0.f;
            a[j] = (tid == j + 32) ? 1.f : 0.f;
        }
        float up[16], vp[16], an[16];
        #pragma unroll
        for (int i = 0; i < 16; i++) {
            up[i] = fmaf(CU_, a[i], fmaf(DTc, v[i], u[i]));
            vp[i] = fmaf(CV_, a[i], v[i]);
        }
        #pragma unroll
        for (int i = 0; i < 16; i++) {
            float s = 0.f;
            #pragma unroll
            for (int j = 0; j < 16; j++)
                s = fmaf(sAv[i*16 + j], vp[j], fmaf(sAu[i*16 + j], up[j], s));
            an[i] = -s;
        }
        #pragma unroll
        for (int i = 0; i < 16; i++) {
            sT[(i)     *NSTATE + tid] = fmaf(BU_, an[i], up[i]);
            sT[(16 + i)*NSTATE + tid] = fmaf(BV_, an[i], vp[i]);
            sT[(32 + i)*NSTATE + tid] = an[i];
        }
    }
    __syncthreads();

    // TL = T^64 via 6 squarings (ping-pong)
    float* Asq = sT;
    float* Bsq = sT2;
    for (int it = 0; it < 6; it++) {
        for (int e = tid; e < NSTATE*NSTATE; e += 256) {
            int r = e / NSTATE, cc = e % NSTATE;
            const float4* rowp = reinterpret_cast<const float4*>(Asq + r*NSTATE);
            float s0 = 0.f, s1 = 0.f, s2 = 0.f, s3 = 0.f;
            #pragma unroll
            for (int q = 0; q < 12; q++) {
                float4 m = rowp[q];
                s0 = fmaf(m.x, Asq[(4*q    )*NSTATE + cc], s0);
                s1 = fmaf(m.y, Asq[(4*q + 1)*NSTATE + cc], s1);
                s2 = fmaf(m.z, Asq[(4*q + 2)*NSTATE + cc], s2);
                s3 = fmaf(m.w, Asq[(4*q + 3)*NSTATE + cc], s3);
            }
            Bsq[e] = (s0 + s1) + (s2 + s3);
        }
        __syncthreads();
        float* t = Asq; Asq = Bsq; Bsq = t;
    }
    for (int e = tid; e < NSTATE*NSTATE; e += 256) g_TL[e] = Asq[e];

    // a0 = Minv @ F[b,0,:], write init_0 and t=0 output row
    for (int idx = tid; idx < BATCH*16; idx += 256) {
        int b = idx >> 4, i = idx & 15;
        const float* f0p = F + (size_t)b * SEQ * N_DOF;
        float s = 0.f;
        #pragma unroll
        for (int j = 0; j < 16; j++) s = fmaf(sMinv[i*16 + j], f0p[j], s);
        float* ip = g_init + (size_t)b * NSTATE;
        ip[i] = 0.f; ip[16 + i] = 0.f; ip[32 + i] = s;
        size_t o = ((size_t)b * SEQ) * N_DOF + i;
        out[o] = 0.f; out[BSD + o] = 0.f; out[2*BSD + o] = s;
    }
}

// ---------------- K_phi: PhiS[b][i][t'] = (Af @ F[b][t'+1])[i], streaming ----------------
__global__ void __launch_bounds__(256) phi_kernel(const float* __restrict__ F)
{
    __shared__ float sAf[256];
    const int tid  = threadIdx.x;
    const int b    = blockIdx.y;
    const int tile = blockIdx.x;           // SEQ/256 tiles
    sAf[tid] = g_Af[tid];
    __syncthreads();

    const int tp = tile * 256 + tid;       // t'
    const int n  = tp + 1;                 // forcing time index

    float ph[16];
    if (n < SEQ) {
        const float4* fp = reinterpret_cast<const float4*>(F + ((size_t)b * SEQ + n) * N_DOF);
        const float4 f0 = fp[0], f1 = fp[1], f2 = fp[2], f3 = fp[3];
        #pragma unroll
        for (int i = 0; i < 16; i++) {
            const float4* ar = reinterpret_cast<const float4*>(sAf + i*16);
            const float4 a0 = ar[0], a1 = ar[1], a2 = ar[2], a3 = ar[3];
            float s0 = 0.f, s1 = 0.f;
            s0 = fmaf(a0.x, f0.x, s0); s1 = fmaf(a0.y, f0.y, s1);
            s0 = fmaf(a0.z, f0.z, s0); s1 = fmaf(a0.w, f0.w, s1);
            s0 = fmaf(a1.x, f1.x, s0); s1 = fmaf(a1.y, f1.y, s1);
            s0 = fmaf(a1.z, f1.z, s0); s1 = fmaf(a1.w, f1.w, s1);
            s0 = fmaf(a2.x, f2.x, s0); s1 = fmaf(a2.y, f2.y, s1);
            s0 = fmaf(a2.z, f2.z, s0); s1 = fmaf(a2.w, f2.w, s1);
            s0 = fmaf(a3.x, f3.x, s0); s1 = fmaf(a3.y, f3.y, s1);
            s0 = fmaf(a3.z, f3.z, s0); s1 = fmaf(a3.w, f3.w, s1);
            ph[i] = s0 + s1;
        }
    } else {
        #pragma unroll
        for (int i = 0; i < 16; i++) ph[i] = 0.f;
    }

    #pragma unroll
    for (int i = 0; i < 16; i++)
        g_PhiS[((size_t)b * N_DOF + i) * SEQ + tp] = ph[i];
}

// ---------------- K1 / K3: chunked scans ----------------
template<bool FINAL>
__global__ void __launch_bounds__(256, 3) scan_kernel(float* __restrict__ out)
{
    const int tid  = threadIdx.x;
    const int lane = tid & 15;
    const int su   = tid >> 4;                 // 0..15
    const int unit = blockIdx.x * 16 + su;
    const int b    = unit & (BATCH - 1);
    const int c    = unit >> 6;

    // exchange weights in registers, packed pairs (Au[j],Av[j])
    const ulonglong2* Wp = reinterpret_cast<const ulonglong2*>(g_Wuv + lane*32);
    const ulonglong2 w0 = Wp[0], w1 = Wp[1], w2 = Wp[2], w3 = Wp[3];
    const ulonglong2 w4 = Wp[4], w5 = Wp[5], w6 = Wp[6], w7 = Wp[7];

    float u, v, a;
    if (FINAL) {
        const float* ip = g_init + ((size_t)c * BATCH + b) * NSTATE;
        u = ip[lane]; v = ip[lane + 16]; a = ip[lane + 32];
    } else {
        u = 0.f; v = 0.f; a = 0.f;
    }

    __shared__ __align__(16) float2 sh[2][16][16];   // double-buffered exchange
    const int t0 = c * CHUNK;

    const float* php = g_PhiS + ((size_t)b * N_DOF + lane) * SEQ + t0;
    float4 ph = *reinterpret_cast<const float4*>(php);   // steps 0..3

    float* outu = out +          ((size_t)b * SEQ + t0 + 1) * N_DOF + lane;
    float* outv = outu + BSD;
    float* outa = outv + BSD;

    #pragma unroll 1
    for (int kg = 0; kg < CHUNK; kg += 4) {
        float4 phn = make_float4(0.f, 0.f, 0.f, 0.f);
        if (kg + 4 < CHUNK) phn = *reinterpret_cast<const float4*>(php + kg + 4);

        #pragma unroll
        for (int s = 0; s < 4; s++) {
            const float phv = (s == 0) ? ph.x : (s == 1) ? ph.y : (s == 2) ? ph.z : ph.w;
            const int buf = s & 1;

            const float up = fmaf(CU_, a, fmaf(DTc, v, u));
            const float vp = fmaf(CV_, a, v);
            sh[buf][su][lane] = make_float2(up, vp);
            __syncwarp();

            const ulonglong2* X2 = reinterpret_cast<const ulonglong2*>(sh[buf][su]);
            u64 accW0 = 0, accW1 = 0;
            {
                ulonglong2 x;
                x = X2[0]; accW0 = ffma2(w0.x, x.x, accW0); accW1 = ffma2(w0.y, x.y, accW1);
                x = X2[1]; accW0 = ffma2(w1.x, x.x, accW0); accW1 = ffma2(w1.y, x.y, accW1);
                x = X2[2]; accW0 = ffma2(w2.x, x.x, accW0); accW1 = ffma2(w2.y, x.y, accW1);
                x = X2[3]; accW0 = ffma2(w3.x, x.x, accW0); accW1 = ffma2(w3.y, x.y, accW1);
                x = X2[4]; accW0 = ffma2(w4.x, x.x, accW0); accW1 = ffma2(w4.y, x.y, accW1);
                x = X2[5]; accW0 = ffma2(w5.x, x.x, accW0); accW1 = ffma2(w5.y, x.y, accW1);
                x = X2[6]; accW0 = ffma2(w6.x, x.x, accW0); accW1 = ffma2(w6.y, x.y, accW1);
                x = X2[7]; accW0 = ffma2(w7.x, x.x, accW0); accW1 = ffma2(w7.y, x.y, accW1);
            }
            const float2 wS = unpack2(fadd2(accW0, accW1));
            const float an = phv - wS.x - wS.y;
            const float un = fmaf(BU_, an, up);
            const float vn = fmaf(BV_, an, vp);

            if (FINAL) {
                const int t = t0 + kg + s + 1;
                if (t < SEQ) {
                    const size_t off = (size_t)(kg + s) * N_DOF;
                    outu[off] = un;
                    outv[off] = vn;
                    outa[off] = an;
                }
            }
            u = un; v = vn; a = an;
        }
        ph = phn;
    }

    if (!FINAL) {
        float* ep = g_e + ((size_t)c * BATCH + b) * NSTATE;
        ep[lane] = u; ep[lane + 16] = v; ep[lane + 32] = a;
    }
}

// ---------------- K2: sequential chunk chain (per batch, packed) ----------------
__global__ void chain_kernel()
{
    const int b = blockIdx.x;
    const int i = threadIdx.x;        // 0..47
    __shared__ __align__(16) float cur[2][NSTATE];

    // T row as 24 packed pairs
    ulonglong2 tl[12];
    {
        const ulonglong2* tp = reinterpret_cast<const ulonglong2*>(g_TL + i*NSTATE);
        #pragma unroll
        for (int q = 0; q < 12; q++) tl[q] = tp[q];
    }

    cur[0][i] = g_init[(size_t)b * NSTATE + i];
    __syncthreads();

    const float* ep = g_e + (size_t)b * NSTATE + i;
    const size_t estride = (size_t)BATCH * NSTATE;

    // prefetch ring (distance 2)
    float ev0 = ep[0];
    float ev1 = (NCHUNK > 2) ? ep[estride] : 0.f;

    int p = 0;
    for (int c = 1; c < NCHUNK; c++) {
        const float ev = ev0;
        ev0 = ev1;
        if (c + 2 < NCHUNK) ev1 = ep[(size_t)(c + 1) * estride];

        const ulonglong2* c2 = reinterpret_cast<const ulonglong2*>(cur[p]);
        u64 a0 = 0, a1 = 0, a2 = 0, a3 = 0;
        #pragma unroll
        for (int q = 0; q < 12; q += 4) {
            ulonglong2 x;
            x = c2[q];     a0 = ffma2(tl[q].x,     x.x, a0); a1 = ffma2(tl[q].y,     x.y, a1);
            x = c2[q + 1]; a2 = ffma2(tl[q + 1].x, x.x, a2); a3 = ffma2(tl[q + 1].y, x.y, a3);
            x = c2[q + 2]; a0 = ffma2(tl[q + 2].x, x.x, a0); a1 = ffma2(tl[q + 2].y, x.y, a1);
            x = c2[q + 3]; a2 = ffma2(tl[q + 3].x, x.x, a2); a3 = ffma2(tl[q + 3].y, x.y, a3);
        }
        const float2 s01 = unpack2(fadd2(a0, a1));
        const float2 s23 = unpack2(fadd2(a2, a3));
        const float r = ((s01.x + s01.y) + (s23.x + s23.y)) + ev;
        g_init[((size_t)c * BATCH + b) * NSTATE + i] = r;
        cur[1 - p][i] = r;
        __syncthreads();
        p ^= 1;
    }
}

// ---------------- launch ----------------
extern "C" void kernel_launch(void* const* d_in, const int* in_sizes, int n_in,
                              void* d_out, int out_size)
{
    const float* F = (const float*)d_in[0];
    const float* M = (const float*)d_in[1];
    const float* C = (const float*)d_in[2];
    const float* K = (const float*)d_in[3];
    float* out = (float*)d_out;

    setup_kernel<<<1, 256>>>(F, M, C, K, out);

    // forcing precompute: PhiS = Af @ F rows, transposed + shifted
    phi_kernel<<<dim3(SEQ/256, BATCH), 256>>>(F);

    // K1: zero-init local scans for chunks 0..NCHUNK-2
    scan_kernel<false><<<(NCHUNK - 1) * BATCH / 16, 256>>>(nullptr);

    // K2: sequential combine across chunks, independent per batch
    chain_kernel<<<BATCH, NSTATE>>>();

    // K3: final scans from correct initial states, all chunks
    scan_kernel<true><<<NCHUNK * BATCH / 16, 256>>>(out);
}

// round 8
// speedup vs baseline: 1.0991x; 1.0219x over previous
#include <cuda_runtime.h>

#define N_DOF 16
#define BATCH 64
#define SEQ 8192
#define CHUNK 64
#define NCHUNK (SEQ/CHUNK)          // 128
#define NSTATE 48
#define BSD ((size_t)BATCH*(size_t)SEQ*(size_t)N_DOF)

#define DTc 0.01f
#define CU_ 2.5e-5f   // (0.5-beta)*dt*dt
#define CV_ 0.005f    // (1-gamma)*dt
#define BU_ 2.5e-5f   // beta*dt*dt
#define BV_ 0.005f    // gamma*dt

// ---------------- packed f32x2 helpers (Blackwell FFMA2) ----------------
typedef unsigned long long u64;

__device__ __forceinline__ u64 ffma2(u64 a, u64 b, u64 c) {
    u64 d;
    asm("fma.rn.f32x2 %0, %1, %2, %3;" : "=l"(d) : "l"(a), "l"(b), "l"(c));
    return d;
}
__device__ __forceinline__ u64 fadd2(u64 a, u64 b) {
    u64 d;
    asm("add.rn.f32x2 %0, %1, %2;" : "=l"(d) : "l"(a), "l"(b));
    return d;
}
__device__ __forceinline__ float2 unpack2(u64 d) {
    float2 f;
    asm("mov.b64 {%0, %1}, %2;" : "=f"(f.x), "=f"(f.y) : "l"(d));
    return f;
}

// ---------------- scratch (device globals; no runtime allocation) ----------------
__device__ __align__(16) float g_Af[256];      // K_eff^{-1}
__device__ __align__(16) float g_Wuv[16*32];   // interleaved pairs: (Au[i][j], Av[i][j])
__device__ __align__(16) float g_TL[NSTATE*NSTATE];
__device__ __align__(16) float g_e[(NCHUNK-1)*BATCH*NSTATE];
__device__ __align__(16) float g_init[NCHUNK*BATCH*NSTATE];
// PhiS[b][i][t'] = (A_f @ F[b, t'+1, :])[i]  for t' in [0, SEQ-1); PhiS[..][SEQ-1] = 0
__device__ __align__(16) float g_PhiS[(size_t)BATCH*N_DOF*SEQ];

// ---------------- K0: setup ----------------
__device__ void invert16(const float* A, float* Ainv, double (*aug)[34], int tid)
{
    if (tid < 16) {
        #pragma unroll
        for (int j = 0; j < 16; j++) {
            aug[tid][j]      = (double)A[tid*16 + j];
            aug[tid][16 + j] = (tid == j) ? 1.0 : 0.0;
        }
    }
    __syncthreads();
    for (int k = 0; k < 16; k++) {
        if (tid == k) {
            double p = 1.0 / aug[k][k];
            #pragma unroll
            for (int j = 0; j < 32; j++) aug[k][j] *= p;
        }
        __syncthreads();
        if (tid < 16 && tid != k) {
            double f = aug[tid][k];
            #pragma unroll
            for (int j = 0; j < 32; j++) aug[tid][j] -= f * aug[k][j];
        }
        __syncthreads();
    }
    if (tid < 16) {
        #pragma unroll
        for (int j = 0; j < 16; j++) Ainv[tid*16 + j] = (float)aug[tid][16 + j];
    }
    __syncthreads();
}

__global__ void setup_kernel(const float* __restrict__ F,
                             const float* __restrict__ M,
                             const float* __restrict__ C,
                             const float* __restrict__ K,
                             float* __restrict__ out)
{
    __shared__ double aug[16][34];
    __shared__ float sM[256], sC[256], sK[256], sKe[256];
    __shared__ float sMinv[256], sAf[256], sAv[256], sAu[256];
    __shared__ __align__(16) float sT[NSTATE*NSTATE];
    __shared__ __align__(16) float sT2[NSTATE*NSTATE];

    const int tid = threadIdx.x;

    sM[tid] = M[tid]; sC[tid] = C[tid]; sK[tid] = K[tid];
    __syncthreads();

    invert16(sM, sMinv, aug, tid);

    sKe[tid] = sM[tid] + 0.5f*DTc*sC[tid] + 0.25f*DTc*DTc*sK[tid];
    __syncthreads();
    invert16(sKe, sAf, aug, tid);

    // A_v = A_f @ C, A_u = A_f @ K
    {
        int i = tid >> 4, j = tid & 15;
        float sv = 0.f, su = 0.f;
        #pragma unroll
        for (int k = 0; k < 16; k++) {
            sv = fmaf(sAf[i*16 + k], sC[k*16 + j], sv);
            su = fmaf(sAf[i*16 + k], sK[k*16 + j], su);
        }
        sAv[tid] = sv; sAu[tid] = su;
    }
    __syncthreads();

    g_Af[tid] = sAf[tid];
    {
        int i = tid >> 4, j = tid & 15;
        g_Wuv[i*32 + 2*j]     = sAu[tid];
        g_Wuv[i*32 + 2*j + 1] = sAv[tid];
    }

    // Build T (48x48) by pushing state basis vectors through one step (f = 0)
    if (tid < NSTATE) {
        float u[16], v[16], a[16];
        #pragma unroll
        for (int j = 0; j < 16; j++) {
            u[j] = (tid == j)      ? 1.f : 0.f;
            v[j] = (tid == j + 16) ? 1.f : 0.f;
            a[j] = (tid == j + 32) ? 1.f : 0.f;
        }
        float up[16], vp[16], an[16];
        #pragma unroll
        for (int i = 0; i < 16; i++) {
            up[i] = fmaf(CU_, a[i], fmaf(DTc, v[i], u[i]));
            vp[i] = fmaf(CV_, a[i], v[i]);
        }
        #pragma unroll
        for (int i = 0; i < 16; i++) {
            float s = 0.f;
            #pragma unroll
            for (int j = 0; j < 16; j++)
                s = fmaf(sAv[i*16 + j], vp[j], fmaf(sAu[i*16 + j], up[j], s));
            an[i] = -s;
        }
        #pragma unroll
        for (int i = 0; i < 16; i++) {
            sT[(i)     *NSTATE + tid] = fmaf(BU_, an[i], up[i]);
            sT[(16 + i)*NSTATE + tid] = fmaf(BV_, an[i], vp[i]);
            sT[(32 + i)*NSTATE + tid] = an[i];
        }
    }
    __syncthreads();

    // TL = T^64 via 6 squarings (ping-pong)
    float* Asq = sT;
    float* Bsq = sT2;
    for (int it = 0; it < 6; it++) {
        for (int e = tid; e < NSTATE*NSTATE; e += 256) {
            int r = e / NSTATE, cc = e % NSTATE;
            const float4* rowp = reinterpret_cast<const float4*>(Asq + r*NSTATE);
            float s0 = 0.f, s1 = 0.f, s2 = 0.f, s3 = 0.f;
            #pragma unroll
            for (int q = 0; q < 12; q++) {
                float4 m = rowp[q];
                s0 = fmaf(m.x, Asq[(4*q    )*NSTATE + cc], s0);
                s1 = fmaf(m.y, Asq[(4*q + 1)*NSTATE + cc], s1);
                s2 = fmaf(m.z, Asq[(4*q + 2)*NSTATE + cc], s2);
                s3 = fmaf(m.w, Asq[(4*q + 3)*NSTATE + cc], s3);
            }
            Bsq[e] = (s0 + s1) + (s2 + s3);
        }
        __syncthreads();
        float* t = Asq; Asq = Bsq; Bsq = t;
    }
    for (int e = tid; e < NSTATE*NSTATE; e += 256) g_TL[e] = Asq[e];

    // a0 = Minv @ F[b,0,:], write init_0 and t=0 output row
    for (int idx = tid; idx < BATCH*16; idx += 256) {
        int b = idx >> 4, i = idx & 15;
        const float* f0p = F + (size_t)b * SEQ * N_DOF;
        float s = 0.f;
        #pragma unroll
        for (int j = 0; j < 16; j++) s = fmaf(sMinv[i*16 + j], f0p[j], s);
        float* ip = g_init + (size_t)b * NSTATE;
        ip[i] = 0.f; ip[16 + i] = 0.f; ip[32 + i] = s;
        size_t o = ((size_t)b * SEQ) * N_DOF + i;
        out[o] = 0.f; out[BSD + o] = 0.f; out[2*BSD + o] = s;
    }
}

// ---------------- K_phi: PhiS[b][i][t'] = (Af @ F[b][t'+1])[i], streaming ----------------
__global__ void __launch_bounds__(256) phi_kernel(const float* __restrict__ F)
{
    __shared__ float sAf[256];
    const int tid  = threadIdx.x;
    const int b    = blockIdx.y;
    const int tile = blockIdx.x;           // SEQ/256 tiles
    sAf[tid] = g_Af[tid];
    __syncthreads();

    const int tp = tile * 256 + tid;       // t'
    const int n  = tp + 1;                 // forcing time index

    float ph[16];
    if (n < SEQ) {
        const float4* fp = reinterpret_cast<const float4*>(F + ((size_t)b * SEQ + n) * N_DOF);
        const float4 f0 = fp[0], f1 = fp[1], f2 = fp[2], f3 = fp[3];
        #pragma unroll
        for (int i = 0; i < 16; i++) {
            const float4* ar = reinterpret_cast<const float4*>(sAf + i*16);
            const float4 a0 = ar[0], a1 = ar[1], a2 = ar[2], a3 = ar[3];
            float s0 = 0.f, s1 = 0.f;
            s0 = fmaf(a0.x, f0.x, s0); s1 = fmaf(a0.y, f0.y, s1);
            s0 = fmaf(a0.z, f0.z, s0); s1 = fmaf(a0.w, f0.w, s1);
            s0 = fmaf(a1.x, f1.x, s0); s1 = fmaf(a1.y, f1.y, s1);
            s0 = fmaf(a1.z, f1.z, s0); s1 = fmaf(a1.w, f1.w, s1);
            s0 = fmaf(a2.x, f2.x, s0); s1 = fmaf(a2.y, f2.y, s1);
            s0 = fmaf(a2.z, f2.z, s0); s1 = fmaf(a2.w, f2.w, s1);
            s0 = fmaf(a3.x, f3.x, s0); s1 = fmaf(a3.y, f3.y, s1);
            s0 = fmaf(a3.z, f3.z, s0); s1 = fmaf(a3.w, f3.w, s1);
            ph[i] = s0 + s1;
        }
    } else {
        #pragma unroll
        for (int i = 0; i < 16; i++) ph[i] = 0.f;
    }

    #pragma unroll
    for (int i = 0; i < 16; i++)
        g_PhiS[((size_t)b * N_DOF + i) * SEQ + tp] = ph[i];
}

// ---------------- K1 / K3: chunked scans ----------------
template<bool FINAL>
__global__ void __launch_bounds__(256, 3) scan_kernel(float* __restrict__ out)
{
    const int tid  = threadIdx.x;
    const int lane = tid & 15;
    const int su   = tid >> 4;                 // 0..15
    const int unit = blockIdx.x * 16 + su;
    const int b    = unit & (BATCH - 1);
    const int c    = unit >> 6;

    // exchange weights in registers, packed pairs (Au[j],Av[j])
    const ulonglong2* Wp = reinterpret_cast<const ulonglong2*>(g_Wuv + lane*32);
    const ulonglong2 w0 = Wp[0], w1 = Wp[1], w2 = Wp[2], w3 = Wp[3];
    const ulonglong2 w4 = Wp[4], w5 = Wp[5], w6 = Wp[6], w7 = Wp[7];

    float u, v, a;
    if (FINAL) {
        const float* ip = g_init + ((size_t)c * BATCH + b) * NSTATE;
        u = ip[lane]; v = ip[lane + 16]; a = ip[lane + 32];
    } else {
        u = 0.f; v = 0.f; a = 0.f;
    }

    __shared__ __align__(16) float2 sh[2][16][16];   // double-buffered exchange
    const int t0 = c * CHUNK;

    const float* php = g_PhiS + ((size_t)b * N_DOF + lane) * SEQ + t0;
    float4 ph = *reinterpret_cast<const float4*>(php);   // steps 0..3

    float* outu = out +          ((size_t)b * SEQ + t0 + 1) * N_DOF + lane;
    float* outv = outu + BSD;
    float* outa = outv + BSD;

    #pragma unroll 1
    for (int kg = 0; kg < CHUNK; kg += 4) {
        float4 phn = make_float4(0.f, 0.f, 0.f, 0.f);
        if (kg + 4 < CHUNK) phn = *reinterpret_cast<const float4*>(php + kg + 4);

        #pragma unroll
        for (int s = 0; s < 4; s++) {
            const float phv = (s == 0) ? ph.x : (s == 1) ? ph.y : (s == 2) ? ph.z : ph.w;
            const int buf = s & 1;

            const float up = fmaf(CU_, a, fmaf(DTc, v, u));
            const float vp = fmaf(CV_, a, v);
            sh[buf][su][lane] = make_float2(up, vp);
            __syncwarp();

            const ulonglong2* X2 = reinterpret_cast<const ulonglong2*>(sh[buf][su]);
            u64 accW0 = 0, accW1 = 0;
            {
                ulonglong2 x;
                x = X2[0]; accW0 = ffma2(w0.x, x.x, accW0); accW1 = ffma2(w0.y, x.y, accW1);
                x = X2[1]; accW0 = ffma2(w1.x, x.x, accW0); accW1 = ffma2(w1.y, x.y, accW1);
                x = X2[2]; accW0 = ffma2(w2.x, x.x, accW0); accW1 = ffma2(w2.y, x.y, accW1);
                x = X2[3]; accW0 = ffma2(w3.x, x.x, accW0); accW1 = ffma2(w3.y, x.y, accW1);
                x = X2[4]; accW0 = ffma2(w4.x, x.x, accW0); accW1 = ffma2(w4.y, x.y, accW1);
                x = X2[5]; accW0 = ffma2(w5.x, x.x, accW0); accW1 = ffma2(w5.y, x.y, accW1);
                x = X2[6]; accW0 = ffma2(w6.x, x.x, accW0); accW1 = ffma2(w6.y, x.y, accW1);
                x = X2[7]; accW0 = ffma2(w7.x, x.x, accW0); accW1 = ffma2(w7.y, x.y, accW1);
            }
            const float2 wS = unpack2(fadd2(accW0, accW1));
            const float an = phv - wS.x - wS.y;
            const float un = fmaf(BU_, an, up);
            const float vn = fmaf(BV_, an, vp);

            if (FINAL) {
                const int t = t0 + kg + s + 1;
                if (t < SEQ) {
                    const size_t off = (size_t)(kg + s) * N_DOF;
                    outu[off] = un;
                    outv[off] = vn;
                    outa[off] = an;
                }
            }
            u = un; v = vn; a = an;
        }
        ph = phn;
    }

    if (!FINAL) {
        float* ep = g_e + ((size_t)c * BATCH + b) * NSTATE;
        ep[lane] = u; ep[lane + 16] = v; ep[lane + 32] = a;
    }
}

// ---------------- K2: sequential chunk chain (per batch, SMEM-staged) ----------------
__global__ void __launch_bounds__(128) chain_kernel()
{
    const int b = blockIdx.x;
    const int tid = threadIdx.x;      // 0..127
    const int i = tid;                // compute lane (only < NSTATE active)

    __shared__ __align__(16) float se[(NCHUNK-1)*NSTATE];   // 24384 B: all e's for this batch
    __shared__ __align__(16) float cur[2][NSTATE];

    // bulk stage: g_e[c][b][:] for all c -> SMEM (high MLP, coalesced 192B rows)
    for (int idx = tid; idx < (NCHUNK-1)*NSTATE; idx += 128) {
        const int c = idx / NSTATE;
        const int j = idx - c * NSTATE;
        se[idx] = g_e[((size_t)c * BATCH + b) * NSTATE + j];
    }

    // T row as 24 packed pairs (threads < NSTATE)
    ulonglong2 tl[12];
    if (i < NSTATE) {
        const ulonglong2* tp = reinterpret_cast<const ulonglong2*>(g_TL + i*NSTATE);
        #pragma unroll
        for (int q = 0; q < 12; q++) tl[q] = tp[q];
        cur[0][i] = g_init[(size_t)b * NSTATE + i];
    }
    __syncthreads();

    int p = 0;
    for (int c = 1; c < NCHUNK; c++) {
        if (i < NSTATE) {
            const float ev = se[(c - 1) * NSTATE + i];
            const ulonglong2* c2 = reinterpret_cast<const ulonglong2*>(cur[p]);
            u64 a0 = 0, a1 = 0, a2 = 0, a3 = 0;
            #pragma unroll
            for (int q = 0; q < 12; q += 4) {
                ulonglong2 x;
                x = c2[q];     a0 = ffma2(tl[q].x,     x.x, a0); a1 = ffma2(tl[q].y,     x.y, a1);
                x = c2[q + 1]; a2 = ffma2(tl[q + 1].x, x.x, a2); a3 = ffma2(tl[q + 1].y, x.y, a3);
                x = c2[q + 2]; a0 = ffma2(tl[q + 2].x, x.x, a0); a1 = ffma2(tl[q + 2].y, x.y, a1);
                x = c2[q + 3]; a2 = ffma2(tl[q + 3].x, x.x, a2); a3 = ffma2(tl[q + 3].y, x.y, a3);
            }
            const float2 s01 = unpack2(fadd2(a0, a1));
            const float2 s23 = unpack2(fadd2(a2, a3));
            const float r = ((s01.x + s01.y) + (s23.x + s23.y)) + ev;
            g_init[((size_t)c * BATCH + b) * NSTATE + i] = r;
            cur[1 - p][i] = r;
        }
        __syncthreads();
        p ^= 1;
    }
}

// ---------------- launch ----------------
extern "C" void kernel_launch(void* const* d_in, const int* in_sizes, int n_in,
                              void* d_out, int out_size)
{
    const float* F = (const float*)d_in[0];
    const float* M = (const float*)d_in[1];
    const float* C = (const float*)d_in[2];
    const float* K = (const float*)d_in[3];
    float* out = (float*)d_out;

    setup_kernel<<<1, 256>>>(F, M, C, K, out);

    // forcing precompute: PhiS = Af @ F rows, transposed + shifted
    phi_kernel<<<dim3(SEQ/256, BATCH), 256>>>(F);

    // K1: zero-init local scans for chunks 0..NCHUNK-2
    scan_kernel<false><<<(NCHUNK - 1) * BATCH / 16, 256>>>(nullptr);

    // K2: sequential combine across chunks, independent per batch
    chain_kernel<<<BATCH, 128>>>();

    // K3: final scans from correct initial states, all chunks
    scan_kernel<true><<<NCHUNK * BATCH / 16, 256>>>(out);
}